// round 16
// baseline (speedup 1.0000x reference)
#include <cuda_runtime.h>
#include <cstdint>

// Problem constants
#define BB   8
#define TT   8
#define DIMD 4096
#define NHH  32
#define NKV  8
#define HD   128
#define PAST 4096
#define TOT  4104          // PAST + T
#define NCH  33            // 32 past chunks of 128 + 1 new chunk of 8
#define NSPL 8             // split-K factor for gemm1 (QKV)
#define NSPL2 16           // split-K factor for gemm2 (output proj)

// Output packing offsets (all elements as float in d_out)
#define OFF_KI8 262144LL
#define N_KI8   134479872LL
#define OFF_KS  (OFF_KI8 + N_KI8)
#define N_SC    1050624LL
#define OFF_VI8 (OFF_KS + N_SC)
#define OFF_VS  (OFF_VI8 + N_KI8)

typedef unsigned long long ull;

// ---------------- scratch ----------------
__device__ float g_part[NSPL2 * 64 * 6144];
__device__ float g_q[BB * NKV * 32 * HD];
__device__ float g_knew[BB * NKV * TT * HD];
__device__ float g_vnew[BB * NKV * TT * HD];
__device__ float g_acc[BB * NKV * NCH * 32 * HD];
__device__ float g_m[BB * NKV * NCH * 32];
__device__ float g_l[BB * NKV * NCH * 32];
__device__ float g_attout[64 * DIMD];

// ---------------- f32x2 helpers ---------------------------------------------
__device__ __forceinline__ ull pack_dup(float x)
{
    ull r;
    asm("mov.b64 %0, {%1, %1};" : "=l"(r) : "f"(x));
    return r;
}
__device__ __forceinline__ void ffma2(ull& acc, ull a, ull b)
{
    asm("fma.rn.f32x2 %0, %1, %2, %0;" : "+l"(acc) : "l"(a), "l"(b));
}
__device__ __forceinline__ void unpack2(ull v, float& lo, float& hi)
{
    asm("mov.b64 {%0, %1}, %2;" : "=f"(lo), "=f"(hi) : "l"(v));
}

// ---------------- async-copy helpers -----------------------------------------
__device__ __forceinline__ uint32_t smem_u32(const void* p)
{
    return (uint32_t)__cvta_generic_to_shared(p);
}
__device__ __forceinline__ void cp16(uint32_t sdst, const void* gsrc)
{
    asm volatile("cp.async.ca.shared.global [%0], [%1], 16;"
                 :: "r"(sdst), "l"(gsrc) : "memory");
}
#define CP_COMMIT() asm volatile("cp.async.commit_group;" ::: "memory")
#define CP_WAIT1()  asm volatile("cp.async.wait_group 1;" ::: "memory")
#define CP_WAIT0()  asm volatile("cp.async.wait_group 0;" ::: "memory")

__device__ __forceinline__ void bulk_s2g(void* gdst, uint32_t ssrc, int bytes)
{
    asm volatile("cp.async.bulk.global.shared::cta.bulk_group [%0], [%1], %2;"
                 :: "l"(gdst), "r"(ssrc), "r"(bytes) : "memory");
}
#define BULK_COMMIT()  asm volatile("cp.async.bulk.commit_group;" ::: "memory")
#define BULK_WAIT_READ1() asm volatile("cp.async.bulk.wait_group.read 1;" ::: "memory")
#define BULK_WAIT_ALL()   asm volatile("cp.async.bulk.wait_group 0;" ::: "memory")
#define FENCE_ASYNC()  asm volatile("fence.proxy.async.shared::cta;" ::: "memory")

// ---------------- GEMM (R13, proven): cp.async double buffer ----------------
__global__ void gemm64(const float* __restrict__ Aext, int useAtt,
                       const float* __restrict__ W1, int N1, int ldw1,
                       const float* __restrict__ W2, int ldw2,
                       int Ntot, int K, int kchunk)
{
    const float* A = useAtt ? g_attout : Aext;
    __shared__ float xs[2][64][36];
    __shared__ float ws[2][32][64];
    const int tid = threadIdx.x;
    const int n0 = blockIdx.x * 64;
    const int ks = blockIdx.y;
    const int kb = ks * kchunk;

    const float* W; int ldw, wc;
    if (n0 < N1) { W = W1; ldw = ldw1; wc = n0; }
    else         { W = W2; ldw = ldw2; wc = n0 - N1; }

    const int tx = tid & 15;
    const int ty = tid >> 4;
    const int xrow = tid >> 3;
    const int xc4 = (tid & 7) * 4;
    const int wrow = tid >> 4;
    const int wc4 = (tid & 15) * 4;

    ull acc2[4][2];
#pragma unroll
    for (int i = 0; i < 4; i++) { acc2[i][0] = 0ull; acc2[i][1] = 0ull; }

    const int T = kchunk / 32;

#pragma unroll
    for (int p = 0; p < 2; p++) {
        const int k0 = kb + p * 32;
        cp16(smem_u32(&xs[p][xrow][xc4]),      A + (long)xrow * K + k0 + xc4);
        cp16(smem_u32(&xs[p][xrow + 32][xc4]), A + (long)(xrow + 32) * K + k0 + xc4);
        cp16(smem_u32(&ws[p][wrow][wc4]),      W + (long)(k0 + wrow) * ldw + wc + wc4);
        cp16(smem_u32(&ws[p][wrow + 16][wc4]), W + (long)(k0 + wrow + 16) * ldw + wc + wc4);
        CP_COMMIT();
    }

#pragma unroll 1
    for (int t = 0; t < T; t++) {
        const int pb = t & 1;
        if (t + 1 < T) CP_WAIT1(); else CP_WAIT0();
        __syncthreads();
#pragma unroll
        for (int kk = 0; kk < 32; kk += 4) {
            float xr[4][4];
#pragma unroll
            for (int i = 0; i < 4; i++)
                *(float4*)xr[i] = *(const float4*)&xs[pb][ty * 4 + i][kk];
#pragma unroll
            for (int j = 0; j < 4; j++) {
                ulonglong2 wv = *(const ulonglong2*)&ws[pb][kk + j][tx * 4];
                ull x0 = pack_dup(xr[0][j]);
                ull x1 = pack_dup(xr[1][j]);
                ull x2 = pack_dup(xr[2][j]);
                ull x3 = pack_dup(xr[3][j]);
                ffma2(acc2[0][0], x0, wv.x); ffma2(acc2[0][1], x0, wv.y);
                ffma2(acc2[1][0], x1, wv.x); ffma2(acc2[1][1], x1, wv.y);
                ffma2(acc2[2][0], x2, wv.x); ffma2(acc2[2][1], x2, wv.y);
                ffma2(acc2[3][0], x3, wv.x); ffma2(acc2[3][1], x3, wv.y);
            }
        }
        __syncthreads();
        if (t + 2 < T) {
            const int k0 = kb + (t + 2) * 32;
            cp16(smem_u32(&xs[pb][xrow][xc4]),      A + (long)xrow * K + k0 + xc4);
            cp16(smem_u32(&xs[pb][xrow + 32][xc4]), A + (long)(xrow + 32) * K + k0 + xc4);
            cp16(smem_u32(&ws[pb][wrow][wc4]),      W + (long)(k0 + wrow) * ldw + wc + wc4);
            cp16(smem_u32(&ws[pb][wrow + 16][wc4]), W + (long)(k0 + wrow + 16) * ldw + wc + wc4);
            CP_COMMIT();
        } else {
            CP_COMMIT();
        }
    }
#pragma unroll
    for (int i = 0; i < 4; i++) {
        long row = (long)(ks * 64 + ty * 4 + i) * Ntot + n0 + tx * 4;
        float a0, a1, a2, a3;
        unpack2(acc2[i][0], a0, a1);
        unpack2(acc2[i][1], a2, a3);
        g_part[row + 0] = a0; g_part[row + 1] = a1;
        g_part[row + 2] = a2; g_part[row + 3] = a3;
    }
}

// Vectorized split-K reduce over NSPL2 partials: float4 per thread.
__global__ void reduce_out(float* __restrict__ out)
{
    const long n4 = 64L * 4096 / 4;   // 65536 float4s
    long i = (long)blockIdx.x * blockDim.x + threadIdx.x;
    if (i < n4) {
        const float4* g4 = (const float4*)g_part;
        float4 s = g4[i];
#pragma unroll
        for (int p = 1; p < NSPL2; p++) {
            float4 v = g4[p * n4 + i];
            s.x += v.x; s.y += v.y; s.z += v.z; s.w += v.w;
        }
        ((float4*)out)[i] = s;
    }
}

// -------- RoPE + new-row quantization (fused with split-K reduce) -----------
__device__ __forceinline__ float inv_freq(int i)
{
    return expf(-(float)i * (9.210340371976184f / 64.0f));
}

__global__ void rope_quant(float* __restrict__ out)
{
    const int idx = blockIdx.x;
    const int d = threadIdx.x;
    __shared__ float srow[128];
    __shared__ float red[4];
    const long NTOT = 64L * 6144;

    if (idx < 2048) {
        int b = idx >> 8, r1 = idx & 255, t = r1 >> 5, h = r1 & 31;
        long base = (long)(b * 8 + t) * 6144 + h * 128 + d;
        float x = 0.f;
#pragma unroll
        for (int p = 0; p < NSPL; p++) x += g_part[(long)p * NTOT + base];
        srow[d] = x;
        __syncthreads();
        int i = d & 63;
        float ang = (float)(PAST + t) * inv_freq(i);
        float partner = srow[d < 64 ? d + 64 : d - 64];
        float rot = (d < 64) ? -partner : partner;
        float y = x * cosf(ang) + rot * sinf(ang);
        int kvh = h >> 2, r = h & 3;
        g_q[(((long)(b * 8 + kvh) * 32) + r * 8 + t) * 128 + d] = y;
    } else {
        const int isV = (idx >= 2560);
        int j = idx - (isV ? 2560 : 2048);
        int b = j >> 6, t = (j >> 3) & 7, kvh = j & 7;
        long base = (long)(b * 8 + t) * 6144 + 4096 + (isV ? 1024 : 0) + kvh * 128 + d;
        float x = 0.f;
#pragma unroll
        for (int p = 0; p < NSPL; p++) x += g_part[(long)p * NTOT + base];
        srow[d] = x;
        __syncthreads();
        float y;
        if (!isV) {
            int i = d & 63;
            float ang = (float)(PAST + t) * inv_freq(i);
            float partner = srow[d < 64 ? d + 64 : d - 64];
            y = x * cosf(ang) + (d < 64 ? -partner : partner) * sinf(ang);
            g_knew[((long)(b * 8 + kvh) * 8 + t) * 128 + d] = y;
        } else {
            y = x;
            g_vnew[((long)(b * 8 + kvh) * 8 + t) * 128 + d] = y;
        }
        float a = fabsf(y);
#pragma unroll
        for (int o = 16; o > 0; o >>= 1) a = fmaxf(a, __shfl_xor_sync(0xffffffffu, a, o));
        if ((d & 31) == 0) red[d >> 5] = a;
        __syncthreads();
        float am = fmaxf(fmaxf(red[0], red[1]), fmaxf(red[2], red[3]));
        float scale = fmaxf(__fdiv_rn(am, 127.0f), 1e-8f);
        float q = fminf(fmaxf(rintf(__fdiv_rn(y, scale)), -127.f), 127.f);
        int pos = PAST + t;
        long offI = isV ? OFF_VI8 : OFF_KI8;
        long offS = isV ? OFF_VS : OFF_KS;
#pragma unroll
        for (int r = 0; r < 4; r++) {
            int h2 = kvh * 4 + r;
            out[offI + ((long)(b * 32 + h2) * TOT + pos) * 128 + d] = q;
            if (d == 0) out[offS + (long)(b * 32 + h2) * TOT + pos] = scale;
        }
    }
}

// ---------------- attention helpers ----------------------------------------

__device__ __forceinline__ float quant1(float v, float inv, float scale)
{
    float t = v * inv;
    float r = rintf(t);
    if (fabsf(fabsf(t - r) - 0.5f) < 1e-4f)
        r = rintf(__fdiv_rn(v, scale));
    return fminf(fmaxf(r, -127.f), 127.f);
}

__device__ __forceinline__ void requant_smem(
    const int4* iv, float s, int rr, int lane8,
    float4* __restrict__ kv4, float4* __restrict__ qst, float* __restrict__ s_scale)
{
    float4 vals[4];
    float am = 0.f;
#pragma unroll
    for (int i = 0; i < 4; i++) {
        vals[i].x = (float)iv[i].x * s;
        vals[i].y = (float)iv[i].y * s;
        vals[i].z = (float)iv[i].z * s;
        vals[i].w = (float)iv[i].w * s;
        am = fmaxf(am, fmaxf(fmaxf(fabsf(vals[i].x), fabsf(vals[i].y)),
                             fmaxf(fabsf(vals[i].z), fabsf(vals[i].w))));
    }
    am = fmaxf(am, __shfl_xor_sync(0xffffffffu, am, 1));
    am = fmaxf(am, __shfl_xor_sync(0xffffffffu, am, 2));
    am = fmaxf(am, __shfl_xor_sync(0xffffffffu, am, 4));
    float scale = fmaxf(__fdiv_rn(am, 127.f), 1e-8f);
    float inv = __fdiv_rn(1.f, scale);

    const int swz = (rr >> 1) & 7;
#pragma unroll
    for (int i = 0; i < 4; i++) {
        float4 qv;
        qv.x = quant1(vals[i].x, inv, scale);
        qv.y = quant1(vals[i].y, inv, scale);
        qv.z = quant1(vals[i].z, inv, scale);
        qv.w = quant1(vals[i].w, inv, scale);
        qst[rr * 32 + lane8 + 8 * i] = qv;
        kv4[rr * 32 + ((lane8 + 8 * i) ^ swz)] = vals[i];
    }
    if (lane8 == 0) s_scale[rr] = scale;
}

__device__ __forceinline__ void issue_bulk(
    float* __restrict__ out, long offI, long offS,
    int b, int kvh, int pos0,
    const float4* __restrict__ qst, const float* __restrict__ s_scale)
{
    FENCE_ASYNC();
    uint32_t ssrc = smem_u32(qst);
    uint32_t sscl = smem_u32(s_scale);
    const long hbase = (long)(b * 32 + kvh * 4);
#pragma unroll
    for (int r = 0; r < 4; r++) {
        bulk_s2g(out + offI + ((hbase + r) * TOT + pos0) * 128, ssrc, 16384);
        bulk_s2g(out + offS + (hbase + r) * TOT + pos0, sscl, 128);
    }
    BULK_COMMIT();
}

// Past-chunk scores: 4q x 2k per thread, d-split across half-warps.
__device__ __forceinline__ void scores_past(
    const float4* __restrict__ qs4, const float4* __restrict__ kv4,
    float sc0[][33], float sc1[][33], int tid)
{
    const int w = tid >> 5, lane = tid & 31;
    const int kg = lane & 15, dh = lane >> 4;
    const int qb = 4 * w;
    const int ra = 2 * kg, rb = ra + 1;
    const int swz = kg & 7;
    const float4* ka4 = kv4 + ra * 32;
    const float4* kb4 = kv4 + rb * 32;
    const float4* q04 = qs4 + (qb + 0) * 32;
    const float4* q14 = qs4 + (qb + 1) * 32;
    const float4* q24 = qs4 + (qb + 2) * 32;
    const float4* q34 = qs4 + (qb + 3) * 32;
    float p00 = 0.f, p01 = 0.f, p10 = 0.f, p11 = 0.f;
    float p20 = 0.f, p21 = 0.f, p30 = 0.f, p31 = 0.f;
#pragma unroll
    for (int t = 0; t < 16; t++) {
        const int d4 = t + 16 * dh;
        float4 ka = ka4[d4 ^ swz];
        float4 kb = kb4[d4 ^ swz];
        float4 q0 = q04[d4];
        float4 q1 = q14[d4];
        p00 += q0.x * ka.x + q0.y * ka.y + q0.z * ka.z + q0.w * ka.w;
        p01 += q0.x * kb.x + q0.y * kb.y + q0.z * kb.z + q0.w * kb.w;
        p10 += q1.x * ka.x + q1.y * ka.y + q1.z * ka.z + q1.w * ka.w;
        p11 += q1.x * kb.x + q1.y * kb.y + q1.z * kb.z + q1.w * kb.w;
        float4 q2 = q24[d4];
        float4 q3 = q34[d4];
        p20 += q2.x * ka.x + q2.y * ka.y + q2.z * ka.z + q2.w * ka.w;
        p21 += q2.x * kb.x + q2.y * kb.y + q2.z * kb.z + q2.w * kb.w;
        p30 += q3.x * ka.x + q3.y * ka.y + q3.z * ka.z + q3.w * ka.w;
        p31 += q3.x * kb.x + q3.y * kb.y + q3.z * kb.z + q3.w * kb.w;
    }
    if (dh == 0) {
        sc0[qb + 0][ra] = p00; sc0[qb + 0][rb] = p01;
        sc0[qb + 1][ra] = p10; sc0[qb + 1][rb] = p11;
        sc0[qb + 2][ra] = p20; sc0[qb + 2][rb] = p21;
        sc0[qb + 3][ra] = p30; sc0[qb + 3][rb] = p31;
    } else {
        sc1[qb + 0][ra] = p00; sc1[qb + 0][rb] = p01;
        sc1[qb + 1][ra] = p10; sc1[qb + 1][rb] = p11;
        sc1[qb + 2][ra] = p20; sc1[qb + 2][rb] = p21;
        sc1[qb + 3][ra] = p30; sc1[qb + 3][rb] = p31;
    }
}

__device__ __forceinline__ void softmax_past(
    float sc[][33], float scP[][33], float* __restrict__ fac,
    int rr, int lane8, float& m_run, float& l_run)
{
    const float SC = 0.08838834764831845f; // 1/sqrt(128)
    const int kk = lane8 * 4;
    float v0 = (sc[rr][kk]     + scP[rr][kk])     * SC;
    float v1 = (sc[rr][kk + 1] + scP[rr][kk + 1]) * SC;
    float v2 = (sc[rr][kk + 2] + scP[rr][kk + 2]) * SC;
    float v3 = (sc[rr][kk + 3] + scP[rr][kk + 3]) * SC;
    float ml = fmaxf(fmaxf(v0, v1), fmaxf(v2, v3));
    ml = fmaxf(ml, __shfl_xor_sync(0xffffffffu, ml, 1));
    ml = fmaxf(ml, __shfl_xor_sync(0xffffffffu, ml, 2));
    ml = fmaxf(ml, __shfl_xor_sync(0xffffffffu, ml, 4));
    float mt = fmaxf(m_run, ml);
    float f = __expf(m_run - mt);
    float p0 = __expf(v0 - mt), p1 = __expf(v1 - mt);
    float p2 = __expf(v2 - mt), p3 = __expf(v3 - mt);
    sc[rr][kk] = p0; sc[rr][kk + 1] = p1; sc[rr][kk + 2] = p2; sc[rr][kk + 3] = p3;
    float ls = p0 + p1 + p2 + p3;
    ls += __shfl_xor_sync(0xffffffffu, ls, 1);
    ls += __shfl_xor_sync(0xffffffffu, ls, 2);
    ls += __shfl_xor_sync(0xffffffffu, ls, 4);
    l_run = l_run * f + ls;
    m_run = mt;
    if (lane8 == 0) fac[rr] = f;
}

__device__ __forceinline__ void scores_phase(
    const float4* __restrict__ qs4, const float4* __restrict__ kv4,
    float sc[][33], int q0, int k0, int s0, int mask8)
{
    const float4* qa4 = qs4 + q0 * 32;
    const float4* qb4 = qa4 + 32;
    const float4* ka4 = kv4 + k0 * 32;
    const float4* kb4 = ka4 + 32;
    float d00 = 0.f, d01 = 0.f, d10 = 0.f, d11 = 0.f;
#pragma unroll
    for (int d4 = 0; d4 < 32; d4++) {
        float4 qa = qa4[d4], qb = qb4[d4];
        float4 ka = ka4[d4 ^ s0], kb = kb4[d4 ^ s0];
        d00 += qa.x * ka.x + qa.y * ka.y + qa.z * ka.z + qa.w * ka.w;
        d01 += qa.x * kb.x + qa.y * kb.y + qa.z * kb.z + qa.w * kb.w;
        d10 += qb.x * ka.x + qb.y * ka.y + qb.z * ka.z + qb.w * ka.w;
        d11 += qb.x * kb.x + qb.y * kb.y + qb.z * kb.z + qb.w * kb.w;
    }
    const float SC = 0.08838834764831845f; // 1/sqrt(128)
    d00 *= SC; d01 *= SC; d10 *= SC; d11 *= SC;
    if (mask8 && k0 >= 8) { d00 = -1e30f; d01 = -1e30f; d10 = -1e30f; d11 = -1e30f; }
    sc[q0][k0] = d00;     sc[q0][k0 + 1] = d01;
    sc[q0 + 1][k0] = d10; sc[q0 + 1][k0 + 1] = d11;
}

__device__ __forceinline__ void softmax_phase(
    float sc[][33], float* __restrict__ fac,
    int rr, int lane8, float& m_run, float& l_run)
{
    const int kk = lane8 * 4;
    float v0 = sc[rr][kk], v1 = sc[rr][kk + 1], v2 = sc[rr][kk + 2], v3 = sc[rr][kk + 3];
    float ml = fmaxf(fmaxf(v0, v1), fmaxf(v2, v3));
    ml = fmaxf(ml, __shfl_xor_sync(0xffffffffu, ml, 1));
    ml = fmaxf(ml, __shfl_xor_sync(0xffffffffu, ml, 2));
    ml = fmaxf(ml, __shfl_xor_sync(0xffffffffu, ml, 4));
    float mt = fmaxf(m_run, ml);
    float f = __expf(m_run - mt);
    float p0 = __expf(v0 - mt), p1 = __expf(v1 - mt);
    float p2 = __expf(v2 - mt), p3 = __expf(v3 - mt);
    sc[rr][kk] = p0; sc[rr][kk + 1] = p1; sc[rr][kk + 2] = p2; sc[rr][kk + 3] = p3;
    float ls = p0 + p1 + p2 + p3;
    ls += __shfl_xor_sync(0xffffffffu, ls, 1);
    ls += __shfl_xor_sync(0xffffffffu, ls, 2);
    ls += __shfl_xor_sync(0xffffffffu, ls, 4);
    l_run = l_run * f + ls;
    m_run = mt;
    if (lane8 == 0) fac[rr] = f;
}

__device__ __forceinline__ void pv_phase(
    const float4* __restrict__ kv4, float sc[][33], const float* __restrict__ fac,
    int q0, int l16, int kmax,
    float4& a00, float4& a01, float4& a10, float4& a11)
{
    float f0 = fac[q0], f1 = fac[q0 + 1];
    a00.x *= f0; a00.y *= f0; a00.z *= f0; a00.w *= f0;
    a01.x *= f0; a01.y *= f0; a01.z *= f0; a01.w *= f0;
    a10.x *= f1; a10.y *= f1; a10.z *= f1; a10.w *= f1;
    a11.x *= f1; a11.y *= f1; a11.z *= f1; a11.w *= f1;
#pragma unroll
    for (int k = 0; k < 32; k++) {
        if (k >= kmax) break;
        float pa = sc[q0][k], pb = sc[q0 + 1][k];
        const float4* vr = kv4 + k * 32;
        int i0 = l16 ^ ((k >> 1) & 7);
        float4 v0 = vr[i0], v1 = vr[i0 + 16];
        a00.x += pa * v0.x; a00.y += pa * v0.y; a00.z += pa * v0.z; a00.w += pa * v0.w;
        a01.x += pa * v1.x; a01.y += pa * v1.y; a01.z += pa * v1.z; a01.w += pa * v1.w;
        a10.x += pb * v0.x; a10.y += pb * v0.y; a10.z += pb * v0.z; a10.w += pb * v0.w;
        a11.x += pb * v1.x; a11.y += pb * v1.y; a11.z += pb * v1.z; a11.w += pb * v1.w;
    }
}

// ---------------- flash attention over one 128-key chunk --------------------
__global__ void __launch_bounds__(256, 2)
att1(const int* __restrict__ pk, const float* __restrict__ pks,
     const int* __restrict__ pvv, const float* __restrict__ pvs,
     float* __restrict__ out)
{
    __shared__ float4 qs4[32 * 32];
    __shared__ float4 kv4[32 * 32];
    __shared__ __align__(16) float4 qkst[32 * 32];
    __shared__ __align__(16) float4 qvst[32 * 32];
    __shared__ __align__(16) float sclK[32];
    __shared__ __align__(16) float sclV[32];
    __shared__ float sc[32][33];
    __shared__ float scP[32][33];
    __shared__ float fac[32];

    const int c = blockIdx.x, kvh = blockIdx.y, b = blockIdx.z;
    const int tid = threadIdx.x;
    const int rr = tid >> 3, lane8 = tid & 7;
    const int tx = tid & 15, ty = tid >> 4;
    const int q0 = 2 * ty, k0 = 2 * tx, s0 = tx & 7;
    const int l16 = tx;

    { // load queries (chunk-strided per lane)
        const float4* s4 = (const float4*)(g_q + ((long)(b * 8 + kvh) * 32 + rr) * 128);
#pragma unroll
        for (int i = 0; i < 4; i++) qs4[rr * 32 + lane8 + 8 * i] = s4[lane8 + 8 * i];
    }

    float4 a00 = {0.f, 0.f, 0.f, 0.f}, a01 = a00, a10 = a00, a11 = a00;
    float m_run = -1e30f, l_run = 0.f;

    if (c < 32) {
        const long gbase = (long)(b * 8 + kvh) * 4096;
        int4 kiv[4], viv[4];
        float skc, svc;
        { // preload K(st=0)
            int pos = c * 128 + rr;
            const int4* p4 = (const int4*)(pk + (gbase + pos) * 128);
#pragma unroll
            for (int i = 0; i < 4; i++) kiv[i] = __ldcs(p4 + lane8 + 8 * i);
            skc = pks[gbase + pos];
        }
#pragma unroll 1
        for (int st = 0; st < 4; st++) {
            const int pos = c * 128 + st * 32 + rr;
            const int pos0 = c * 128 + st * 32;
            requant_smem(kiv, skc, rr, lane8, kv4, qkst, sclK);
            {
                const int4* p4 = (const int4*)(pvv + (gbase + pos) * 128);
#pragma unroll
                for (int i = 0; i < 4; i++) viv[i] = __ldcs(p4 + lane8 + 8 * i);
                svc = pvs[gbase + pos];
            }
            if (st < 3) {
                const int4* p4 = (const int4*)(pk + (gbase + pos + 32) * 128);
#pragma unroll
                for (int i = 0; i < 4; i++) kiv[i] = __ldcs(p4 + lane8 + 8 * i);
                skc = pks[gbase + pos + 32];
            }
            __syncthreads();
            if (tid == 0) {
                issue_bulk(out, OFF_KI8, OFF_KS, b, kvh, pos0, qkst, sclK);
                BULK_WAIT_READ1();
            }
            scores_past(qs4, kv4, sc, scP, tid);
            __syncthreads();
            softmax_past(sc, scP, fac, rr, lane8, m_run, l_run);
            requant_smem(viv, svc, rr, lane8, kv4, qvst, sclV);
            __syncthreads();
            if (tid == 0) {
                issue_bulk(out, OFF_VI8, OFF_VS, b, kvh, pos0, qvst, sclV);
                BULK_WAIT_READ1();
            }
            pv_phase(kv4, sc, fac, q0, l16, 32, a00, a01, a10, a11);
            __syncthreads();
        }
        if (tid == 0) BULK_WAIT_ALL();
    } else {
        const int swz = (rr >> 1) & 7;
        { // K (8 new rows, rest zero)
            float4 z = {0.f, 0.f, 0.f, 0.f};
            if (rr < 8) {
                const float4* s4 = (const float4*)(g_knew + ((long)(b * 8 + kvh) * 8 + rr) * 128);
#pragma unroll
                for (int i = 0; i < 4; i++) kv4[rr * 32 + ((lane8 + 8 * i) ^ swz)] = s4[lane8 + 8 * i];
            } else {
#pragma unroll
                for (int i = 0; i < 4; i++) kv4[rr * 32 + ((lane8 + 8 * i) ^ swz)] = z;
            }
        }
        __syncthreads();
        scores_phase(qs4, kv4, sc, q0, k0, s0, 1);
        __syncthreads();
        softmax_phase(sc, fac, rr, lane8, m_run, l_run);
        { // V
            float4 z = {0.f, 0.f, 0.f, 0.f};
            if (rr < 8) {
                const float4* s4 = (const float4*)(g_vnew + ((long)(b * 8 + kvh) * 8 + rr) * 128);
#pragma unroll
                for (int i = 0; i < 4; i++) kv4[rr * 32 + ((lane8 + 8 * i) ^ swz)] = s4[lane8 + 8 * i];
            } else {
#pragma unroll
                for (int i = 0; i < 4; i++) kv4[rr * 32 + ((lane8 + 8 * i) ^ swz)] = z;
            }
        }
        __syncthreads();
        pv_phase(kv4, sc, fac, q0, l16, 8, a00, a01, a10, a11);
    }

    // write partials
    {
        const long base = ((long)(b * 8 + kvh) * NCH + c) * 32;
        float4* g4 = (float4*)g_acc;
        g4[(base + q0) * 32 + l16]          = a00;
        g4[(base + q0) * 32 + l16 + 16]     = a01;
        g4[(base + q0 + 1) * 32 + l16]      = a10;
        g4[(base + q0 + 1) * 32 + l16 + 16] = a11;
        if (lane8 == 0) {
            g_m[base + rr] = m_run;
            g_l[base + rr] = l_run;
        }
    }
}

// --------- combine chunk partials: 2 half-warps per query, c-range split ----
// grid 512 x 256: block handles 4 (qi,kvh,b) groups; each group = 64 threads
// (2 half-warp teams splitting the 33 chunks), lane owns a 16B d-slice.
__global__ void att2()
{
    __shared__ float Mb[4][2];
    __shared__ float Lb[4];
    __shared__ float4 obuf[4][32];

    const int tid = threadIdx.x;
    const int g = tid >> 6;                 // group within block (0..3)
    const int half = (tid >> 5) & 1;        // c-range half
    const int d4 = tid & 31;
    const int gid = blockIdx.x * 4 + g;     // 0..2047
    const int qi = gid & 31, kvh = (gid >> 5) & 7, b = gid >> 8;
    const long base = ((long)(b * 8 + kvh) * NCH) * 32 + qi;

    const int cbeg = half ? 17 : 0;
    const int cend = half ? 33 : 17;

    float Mloc = -1e30f;
#pragma unroll
    for (int c = cbeg; c < cend; c++)
        Mloc = fmaxf(Mloc, g_m[base + (long)c * 32]);
    if (d4 == 0) Mb[g][half] = Mloc;
    __syncthreads();
    const float M = fmaxf(Mb[g][0], Mb[g][1]);

    float L = 0.f;
    float4 o = {0.f, 0.f, 0.f, 0.f};
    const float4* g4 = (const float4*)g_acc;
#pragma unroll
    for (int c = cbeg; c < cend; c++) {
        float w = expf(g_m[base + (long)c * 32] - M);
        L += g_l[base + (long)c * 32] * w;
        float4 v = g4[(base + (long)c * 32) * 32 + d4];
        o.x += v.x * w; o.y += v.y * w; o.z += v.z * w; o.w += v.w * w;
    }
    if (half == 1) {
        obuf[g][d4] = o;
        if (d4 == 0) Lb[g] = L;
    }
    __syncthreads();
    if (half == 0) {
        float4 ob = obuf[g][d4];
        o.x += ob.x; o.y += ob.y; o.z += ob.z; o.w += ob.w;
        L += Lb[g];
        float4 res;
        res.x = __fdiv_rn(o.x, L);
        res.y = __fdiv_rn(o.y, L);
        res.z = __fdiv_rn(o.z, L);
        res.w = __fdiv_rn(o.w, L);
        int h = kvh * 4 + (qi >> 3), t = qi & 7;
        *(float4*)(g_attout + (long)(b * 8 + t) * 4096 + h * 128 + d4 * 4) = res;
    }
}

// ---------------- host launcher -------------------------------------------
extern "C" void kernel_launch(void* const* d_in, const int* in_sizes, int n_in,
                              void* d_out, int out_size)
{
    const float* x   = (const float*)d_in[0];
    const float* Wq  = (const float*)d_in[1];
    const float* Wkv = (const float*)d_in[2];
    const float* Wo  = (const float*)d_in[3];
    const int*   pk  = (const int*)d_in[4];
    const float* pks = (const float*)d_in[5];
    const int*   pv  = (const int*)d_in[6];
    const float* pvs = (const float*)d_in[7];
    float* out = (float*)d_out;

    gemm64<<<dim3(96, NSPL), 256>>>(x, 0, Wq, 4096, 4096, Wkv, 2048, 6144, 4096, 512);

    rope_quant<<<3072, 128>>>(out);

    att1<<<dim3(NCH, NKV, BB), 256>>>(pk, pks, pv, pvs, out);

    att2<<<512, 256>>>();

    gemm64<<<dim3(64, NSPL2), 256>>>(x, 1, Wo, 4096, 4096, Wo, 4096, 4096, 4096, 256);
    reduce_out<<<256, 256>>>(out);
}

// round 17
// speedup vs baseline: 1.0252x; 1.0252x over previous
#include <cuda_runtime.h>
#include <cstdint>

// Problem constants
#define BB   8
#define TT   8
#define DIMD 4096
#define NHH  32
#define NKV  8
#define HD   128
#define PAST 4096
#define TOT  4104          // PAST + T
#define NCH  33            // 32 past chunks of 128 + 1 new chunk of 8
#define NSPL 8             // split-K factor for gemm1 (QKV)
#define NSPL2 16           // split-K factor for gemm2 (output proj)

// Output packing offsets (all elements as float in d_out)
#define OFF_KI8 262144LL
#define N_KI8   134479872LL
#define OFF_KS  (OFF_KI8 + N_KI8)
#define N_SC    1050624LL
#define OFF_VI8 (OFF_KS + N_SC)
#define OFF_VS  (OFF_VI8 + N_KI8)

typedef unsigned long long ull;

// ---------------- scratch ----------------
__device__ float g_part[NSPL2 * 64 * 6144];
__device__ float g_q[BB * NKV * 32 * HD];
__device__ float g_knew[BB * NKV * TT * HD];
__device__ float g_vnew[BB * NKV * TT * HD];
__device__ float g_acc[BB * NKV * NCH * 32 * HD];
__device__ float g_m[BB * NKV * NCH * 32];
__device__ float g_l[BB * NKV * NCH * 32];
__device__ float g_attout[64 * DIMD];

// ---------------- f32x2 helpers ---------------------------------------------
__device__ __forceinline__ ull pack_dup(float x)
{
    ull r;
    asm("mov.b64 %0, {%1, %1};" : "=l"(r) : "f"(x));
    return r;
}
__device__ __forceinline__ void ffma2(ull& acc, ull a, ull b)
{
    asm("fma.rn.f32x2 %0, %1, %2, %0;" : "+l"(acc) : "l"(a), "l"(b));
}
__device__ __forceinline__ void unpack2(ull v, float& lo, float& hi)
{
    asm("mov.b64 {%0, %1}, %2;" : "=f"(lo), "=f"(hi) : "l"(v));
}

// ---------------- async-copy helpers -----------------------------------------
__device__ __forceinline__ uint32_t smem_u32(const void* p)
{
    return (uint32_t)__cvta_generic_to_shared(p);
}
__device__ __forceinline__ void cp16(uint32_t sdst, const void* gsrc)
{
    asm volatile("cp.async.ca.shared.global [%0], [%1], 16;"
                 :: "r"(sdst), "l"(gsrc) : "memory");
}
#define CP_COMMIT() asm volatile("cp.async.commit_group;" ::: "memory")
#define CP_WAIT1()  asm volatile("cp.async.wait_group 1;" ::: "memory")
#define CP_WAIT0()  asm volatile("cp.async.wait_group 0;" ::: "memory")

__device__ __forceinline__ void bulk_s2g(void* gdst, uint32_t ssrc, int bytes)
{
    asm volatile("cp.async.bulk.global.shared::cta.bulk_group [%0], [%1], %2;"
                 :: "l"(gdst), "r"(ssrc), "r"(bytes) : "memory");
}
#define BULK_COMMIT()  asm volatile("cp.async.bulk.commit_group;" ::: "memory")
#define BULK_WAIT_READ1() asm volatile("cp.async.bulk.wait_group.read 1;" ::: "memory")
#define BULK_WAIT_ALL()   asm volatile("cp.async.bulk.wait_group 0;" ::: "memory")
#define FENCE_ASYNC()  asm volatile("fence.proxy.async.shared::cta;" ::: "memory")

// ---------------- GEMM (R13, proven): cp.async double buffer ----------------
__global__ void gemm64(const float* __restrict__ Aext, int useAtt,
                       const float* __restrict__ W1, int N1, int ldw1,
                       const float* __restrict__ W2, int ldw2,
                       int Ntot, int K, int kchunk)
{
    const float* A = useAtt ? g_attout : Aext;
    __shared__ float xs[2][64][36];
    __shared__ float ws[2][32][64];
    const int tid = threadIdx.x;
    const int n0 = blockIdx.x * 64;
    const int ks = blockIdx.y;
    const int kb = ks * kchunk;

    const float* W; int ldw, wc;
    if (n0 < N1) { W = W1; ldw = ldw1; wc = n0; }
    else         { W = W2; ldw = ldw2; wc = n0 - N1; }

    const int tx = tid & 15;
    const int ty = tid >> 4;
    const int xrow = tid >> 3;
    const int xc4 = (tid & 7) * 4;
    const int wrow = tid >> 4;
    const int wc4 = (tid & 15) * 4;

    ull acc2[4][2];
#pragma unroll
    for (int i = 0; i < 4; i++) { acc2[i][0] = 0ull; acc2[i][1] = 0ull; }

    const int T = kchunk / 32;

#pragma unroll
    for (int p = 0; p < 2; p++) {
        const int k0 = kb + p * 32;
        cp16(smem_u32(&xs[p][xrow][xc4]),      A + (long)xrow * K + k0 + xc4);
        cp16(smem_u32(&xs[p][xrow + 32][xc4]), A + (long)(xrow + 32) * K + k0 + xc4);
        cp16(smem_u32(&ws[p][wrow][wc4]),      W + (long)(k0 + wrow) * ldw + wc + wc4);
        cp16(smem_u32(&ws[p][wrow + 16][wc4]), W + (long)(k0 + wrow + 16) * ldw + wc + wc4);
        CP_COMMIT();
    }

#pragma unroll 1
    for (int t = 0; t < T; t++) {
        const int pb = t & 1;
        if (t + 1 < T) CP_WAIT1(); else CP_WAIT0();
        __syncthreads();
#pragma unroll
        for (int kk = 0; kk < 32; kk += 4) {
            float xr[4][4];
#pragma unroll
            for (int i = 0; i < 4; i++)
                *(float4*)xr[i] = *(const float4*)&xs[pb][ty * 4 + i][kk];
#pragma unroll
            for (int j = 0; j < 4; j++) {
                ulonglong2 wv = *(const ulonglong2*)&ws[pb][kk + j][tx * 4];
                ull x0 = pack_dup(xr[0][j]);
                ull x1 = pack_dup(xr[1][j]);
                ull x2 = pack_dup(xr[2][j]);
                ull x3 = pack_dup(xr[3][j]);
                ffma2(acc2[0][0], x0, wv.x); ffma2(acc2[0][1], x0, wv.y);
                ffma2(acc2[1][0], x1, wv.x); ffma2(acc2[1][1], x1, wv.y);
                ffma2(acc2[2][0], x2, wv.x); ffma2(acc2[2][1], x2, wv.y);
                ffma2(acc2[3][0], x3, wv.x); ffma2(acc2[3][1], x3, wv.y);
            }
        }
        __syncthreads();
        if (t + 2 < T) {
            const int k0 = kb + (t + 2) * 32;
            cp16(smem_u32(&xs[pb][xrow][xc4]),      A + (long)xrow * K + k0 + xc4);
            cp16(smem_u32(&xs[pb][xrow + 32][xc4]), A + (long)(xrow + 32) * K + k0 + xc4);
            cp16(smem_u32(&ws[pb][wrow][wc4]),      W + (long)(k0 + wrow) * ldw + wc + wc4);
            cp16(smem_u32(&ws[pb][wrow + 16][wc4]), W + (long)(k0 + wrow + 16) * ldw + wc + wc4);
            CP_COMMIT();
        } else {
            CP_COMMIT();
        }
    }
#pragma unroll
    for (int i = 0; i < 4; i++) {
        long row = (long)(ks * 64 + ty * 4 + i) * Ntot + n0 + tx * 4;
        float a0, a1, a2, a3;
        unpack2(acc2[i][0], a0, a1);
        unpack2(acc2[i][1], a2, a3);
        g_part[row + 0] = a0; g_part[row + 1] = a1;
        g_part[row + 2] = a2; g_part[row + 3] = a3;
    }
}

// Vectorized split-K reduce over NSPL2 partials: float4 per thread.
__global__ void reduce_out(float* __restrict__ out)
{
    const long n4 = 64L * 4096 / 4;   // 65536 float4s
    long i = (long)blockIdx.x * blockDim.x + threadIdx.x;
    if (i < n4) {
        const float4* g4 = (const float4*)g_part;
        float4 s = g4[i];
#pragma unroll
        for (int p = 1; p < NSPL2; p++) {
            float4 v = g4[p * n4 + i];
            s.x += v.x; s.y += v.y; s.z += v.z; s.w += v.w;
        }
        ((float4*)out)[i] = s;
    }
}

// -------- RoPE + new-row quantization (fused with split-K reduce) -----------
__device__ __forceinline__ float inv_freq(int i)
{
    return expf(-(float)i * (9.210340371976184f / 64.0f));
}

__global__ void rope_quant(float* __restrict__ out)
{
    const int idx = blockIdx.x;
    const int d = threadIdx.x;
    __shared__ float srow[128];
    __shared__ float red[4];
    const long NTOT = 64L * 6144;

    if (idx < 2048) {
        int b = idx >> 8, r1 = idx & 255, t = r1 >> 5, h = r1 & 31;
        long base = (long)(b * 8 + t) * 6144 + h * 128 + d;
        float x = 0.f;
#pragma unroll
        for (int p = 0; p < NSPL; p++) x += g_part[(long)p * NTOT + base];
        srow[d] = x;
        __syncthreads();
        int i = d & 63;
        float ang = (float)(PAST + t) * inv_freq(i);
        float partner = srow[d < 64 ? d + 64 : d - 64];
        float rot = (d < 64) ? -partner : partner;
        float y = x * cosf(ang) + rot * sinf(ang);
        int kvh = h >> 2, r = h & 3;
        g_q[(((long)(b * 8 + kvh) * 32) + r * 8 + t) * 128 + d] = y;
    } else {
        const int isV = (idx >= 2560);
        int j = idx - (isV ? 2560 : 2048);
        int b = j >> 6, t = (j >> 3) & 7, kvh = j & 7;
        long base = (long)(b * 8 + t) * 6144 + 4096 + (isV ? 1024 : 0) + kvh * 128 + d;
        float x = 0.f;
#pragma unroll
        for (int p = 0; p < NSPL; p++) x += g_part[(long)p * NTOT + base];
        srow[d] = x;
        __syncthreads();
        float y;
        if (!isV) {
            int i = d & 63;
            float ang = (float)(PAST + t) * inv_freq(i);
            float partner = srow[d < 64 ? d + 64 : d - 64];
            y = x * cosf(ang) + (d < 64 ? -partner : partner) * sinf(ang);
            g_knew[((long)(b * 8 + kvh) * 8 + t) * 128 + d] = y;
        } else {
            y = x;
            g_vnew[((long)(b * 8 + kvh) * 8 + t) * 128 + d] = y;
        }
        float a = fabsf(y);
#pragma unroll
        for (int o = 16; o > 0; o >>= 1) a = fmaxf(a, __shfl_xor_sync(0xffffffffu, a, o));
        if ((d & 31) == 0) red[d >> 5] = a;
        __syncthreads();
        float am = fmaxf(fmaxf(red[0], red[1]), fmaxf(red[2], red[3]));
        float scale = fmaxf(__fdiv_rn(am, 127.0f), 1e-8f);
        float q = fminf(fmaxf(rintf(__fdiv_rn(y, scale)), -127.f), 127.f);
        int pos = PAST + t;
        long offI = isV ? OFF_VI8 : OFF_KI8;
        long offS = isV ? OFF_VS : OFF_KS;
#pragma unroll
        for (int r = 0; r < 4; r++) {
            int h2 = kvh * 4 + r;
            out[offI + ((long)(b * 32 + h2) * TOT + pos) * 128 + d] = q;
            if (d == 0) out[offS + (long)(b * 32 + h2) * TOT + pos] = scale;
        }
    }
}

// ---------------- attention helpers ----------------------------------------

__device__ __forceinline__ float quant1(float v, float inv, float scale)
{
    float t = v * inv;
    float r = rintf(t);
    if (fabsf(fabsf(t - r) - 0.5f) < 1e-4f)
        r = rintf(__fdiv_rn(v, scale));
    return fminf(fmaxf(r, -127.f), 127.f);
}

__device__ __forceinline__ void requant_smem(
    const int4* iv, float s, int rr, int lane8,
    float4* __restrict__ kv4, float4* __restrict__ qst, float* __restrict__ s_scale)
{
    float4 vals[4];
    float am = 0.f;
#pragma unroll
    for (int i = 0; i < 4; i++) {
        vals[i].x = (float)iv[i].x * s;
        vals[i].y = (float)iv[i].y * s;
        vals[i].z = (float)iv[i].z * s;
        vals[i].w = (float)iv[i].w * s;
        am = fmaxf(am, fmaxf(fmaxf(fabsf(vals[i].x), fabsf(vals[i].y)),
                             fmaxf(fabsf(vals[i].z), fabsf(vals[i].w))));
    }
    am = fmaxf(am, __shfl_xor_sync(0xffffffffu, am, 1));
    am = fmaxf(am, __shfl_xor_sync(0xffffffffu, am, 2));
    am = fmaxf(am, __shfl_xor_sync(0xffffffffu, am, 4));
    float scale = fmaxf(__fdiv_rn(am, 127.f), 1e-8f);
    float inv = __fdiv_rn(1.f, scale);

    const int swz = (rr >> 1) & 7;
#pragma unroll
    for (int i = 0; i < 4; i++) {
        float4 qv;
        qv.x = quant1(vals[i].x, inv, scale);
        qv.y = quant1(vals[i].y, inv, scale);
        qv.z = quant1(vals[i].z, inv, scale);
        qv.w = quant1(vals[i].w, inv, scale);
        qst[rr * 32 + lane8 + 8 * i] = qv;
        kv4[rr * 32 + ((lane8 + 8 * i) ^ swz)] = vals[i];
    }
    if (lane8 == 0) s_scale[rr] = scale;
}

__device__ __forceinline__ void issue_bulk(
    float* __restrict__ out, long offI, long offS,
    int b, int kvh, int pos0,
    const float4* __restrict__ qst, const float* __restrict__ s_scale)
{
    FENCE_ASYNC();
    uint32_t ssrc = smem_u32(qst);
    uint32_t sscl = smem_u32(s_scale);
    const long hbase = (long)(b * 32 + kvh * 4);
#pragma unroll
    for (int r = 0; r < 4; r++) {
        bulk_s2g(out + offI + ((hbase + r) * TOT + pos0) * 128, ssrc, 16384);
        bulk_s2g(out + offS + (hbase + r) * TOT + pos0, sscl, 128);
    }
    BULK_COMMIT();
}

// Past-chunk scores: 4q x 2k per thread, d-split across half-warps.
__device__ __forceinline__ void scores_past(
    const float4* __restrict__ qs4, const float4* __restrict__ kv4,
    float sc0[][33], float sc1[][33], int tid)
{
    const int w = tid >> 5, lane = tid & 31;
    const int kg = lane & 15, dh = lane >> 4;
    const int qb = 4 * w;
    const int ra = 2 * kg, rb = ra + 1;
    const int swz = kg & 7;
    const float4* ka4 = kv4 + ra * 32;
    const float4* kb4 = kv4 + rb * 32;
    const float4* q04 = qs4 + (qb + 0) * 32;
    const float4* q14 = qs4 + (qb + 1) * 32;
    const float4* q24 = qs4 + (qb + 2) * 32;
    const float4* q34 = qs4 + (qb + 3) * 32;
    float p00 = 0.f, p01 = 0.f, p10 = 0.f, p11 = 0.f;
    float p20 = 0.f, p21 = 0.f, p30 = 0.f, p31 = 0.f;
#pragma unroll
    for (int t = 0; t < 16; t++) {
        const int d4 = t + 16 * dh;
        float4 ka = ka4[d4 ^ swz];
        float4 kb = kb4[d4 ^ swz];
        float4 q0 = q04[d4];
        float4 q1 = q14[d4];
        p00 += q0.x * ka.x + q0.y * ka.y + q0.z * ka.z + q0.w * ka.w;
        p01 += q0.x * kb.x + q0.y * kb.y + q0.z * kb.z + q0.w * kb.w;
        p10 += q1.x * ka.x + q1.y * ka.y + q1.z * ka.z + q1.w * ka.w;
        p11 += q1.x * kb.x + q1.y * kb.y + q1.z * kb.z + q1.w * kb.w;
        float4 q2 = q24[d4];
        float4 q3 = q34[d4];
        p20 += q2.x * ka.x + q2.y * ka.y + q2.z * ka.z + q2.w * ka.w;
        p21 += q2.x * kb.x + q2.y * kb.y + q2.z * kb.z + q2.w * kb.w;
        p30 += q3.x * ka.x + q3.y * ka.y + q3.z * ka.z + q3.w * ka.w;
        p31 += q3.x * kb.x + q3.y * kb.y + q3.z * kb.z + q3.w * kb.w;
    }
    if (dh == 0) {
        sc0[qb + 0][ra] = p00; sc0[qb + 0][rb] = p01;
        sc0[qb + 1][ra] = p10; sc0[qb + 1][rb] = p11;
        sc0[qb + 2][ra] = p20; sc0[qb + 2][rb] = p21;
        sc0[qb + 3][ra] = p30; sc0[qb + 3][rb] = p31;
    } else {
        sc1[qb + 0][ra] = p00; sc1[qb + 0][rb] = p01;
        sc1[qb + 1][ra] = p10; sc1[qb + 1][rb] = p11;
        sc1[qb + 2][ra] = p20; sc1[qb + 2][rb] = p21;
        sc1[qb + 3][ra] = p30; sc1[qb + 3][rb] = p31;
    }
}

__device__ __forceinline__ void softmax_past(
    float sc[][33], float scP[][33], float* __restrict__ fac,
    int rr, int lane8, float& m_run, float& l_run)
{
    const float SC = 0.08838834764831845f; // 1/sqrt(128)
    const int kk = lane8 * 4;
    float v0 = (sc[rr][kk]     + scP[rr][kk])     * SC;
    float v1 = (sc[rr][kk + 1] + scP[rr][kk + 1]) * SC;
    float v2 = (sc[rr][kk + 2] + scP[rr][kk + 2]) * SC;
    float v3 = (sc[rr][kk + 3] + scP[rr][kk + 3]) * SC;
    float ml = fmaxf(fmaxf(v0, v1), fmaxf(v2, v3));
    ml = fmaxf(ml, __shfl_xor_sync(0xffffffffu, ml, 1));
    ml = fmaxf(ml, __shfl_xor_sync(0xffffffffu, ml, 2));
    ml = fmaxf(ml, __shfl_xor_sync(0xffffffffu, ml, 4));
    float mt = fmaxf(m_run, ml);
    float f = __expf(m_run - mt);
    float p0 = __expf(v0 - mt), p1 = __expf(v1 - mt);
    float p2 = __expf(v2 - mt), p3 = __expf(v3 - mt);
    sc[rr][kk] = p0; sc[rr][kk + 1] = p1; sc[rr][kk + 2] = p2; sc[rr][kk + 3] = p3;
    float ls = p0 + p1 + p2 + p3;
    ls += __shfl_xor_sync(0xffffffffu, ls, 1);
    ls += __shfl_xor_sync(0xffffffffu, ls, 2);
    ls += __shfl_xor_sync(0xffffffffu, ls, 4);
    l_run = l_run * f + ls;
    m_run = mt;
    if (lane8 == 0) fac[rr] = f;
}

__device__ __forceinline__ void scores_phase(
    const float4* __restrict__ qs4, const float4* __restrict__ kv4,
    float sc[][33], int q0, int k0, int s0, int mask8)
{
    const float4* qa4 = qs4 + q0 * 32;
    const float4* qb4 = qa4 + 32;
    const float4* ka4 = kv4 + k0 * 32;
    const float4* kb4 = ka4 + 32;
    float d00 = 0.f, d01 = 0.f, d10 = 0.f, d11 = 0.f;
#pragma unroll
    for (int d4 = 0; d4 < 32; d4++) {
        float4 qa = qa4[d4], qb = qb4[d4];
        float4 ka = ka4[d4 ^ s0], kb = kb4[d4 ^ s0];
        d00 += qa.x * ka.x + qa.y * ka.y + qa.z * ka.z + qa.w * ka.w;
        d01 += qa.x * kb.x + qa.y * kb.y + qa.z * kb.z + qa.w * kb.w;
        d10 += qb.x * ka.x + qb.y * ka.y + qb.z * ka.z + qb.w * ka.w;
        d11 += qb.x * kb.x + qb.y * kb.y + qb.z * kb.z + qb.w * kb.w;
    }
    const float SC = 0.08838834764831845f; // 1/sqrt(128)
    d00 *= SC; d01 *= SC; d10 *= SC; d11 *= SC;
    if (mask8 && k0 >= 8) { d00 = -1e30f; d01 = -1e30f; d10 = -1e30f; d11 = -1e30f; }
    sc[q0][k0] = d00;     sc[q0][k0 + 1] = d01;
    sc[q0 + 1][k0] = d10; sc[q0 + 1][k0 + 1] = d11;
}

__device__ __forceinline__ void softmax_phase(
    float sc[][33], float* __restrict__ fac,
    int rr, int lane8, float& m_run, float& l_run)
{
    const int kk = lane8 * 4;
    float v0 = sc[rr][kk], v1 = sc[rr][kk + 1], v2 = sc[rr][kk + 2], v3 = sc[rr][kk + 3];
    float ml = fmaxf(fmaxf(v0, v1), fmaxf(v2, v3));
    ml = fmaxf(ml, __shfl_xor_sync(0xffffffffu, ml, 1));
    ml = fmaxf(ml, __shfl_xor_sync(0xffffffffu, ml, 2));
    ml = fmaxf(ml, __shfl_xor_sync(0xffffffffu, ml, 4));
    float mt = fmaxf(m_run, ml);
    float f = __expf(m_run - mt);
    float p0 = __expf(v0 - mt), p1 = __expf(v1 - mt);
    float p2 = __expf(v2 - mt), p3 = __expf(v3 - mt);
    sc[rr][kk] = p0; sc[rr][kk + 1] = p1; sc[rr][kk + 2] = p2; sc[rr][kk + 3] = p3;
    float ls = p0 + p1 + p2 + p3;
    ls += __shfl_xor_sync(0xffffffffu, ls, 1);
    ls += __shfl_xor_sync(0xffffffffu, ls, 2);
    ls += __shfl_xor_sync(0xffffffffu, ls, 4);
    l_run = l_run * f + ls;
    m_run = mt;
    if (lane8 == 0) fac[rr] = f;
}

__device__ __forceinline__ void pv_phase(
    const float4* __restrict__ kv4, float sc[][33], const float* __restrict__ fac,
    int q0, int l16, int kmax,
    float4& a00, float4& a01, float4& a10, float4& a11)
{
    float f0 = fac[q0], f1 = fac[q0 + 1];
    a00.x *= f0; a00.y *= f0; a00.z *= f0; a00.w *= f0;
    a01.x *= f0; a01.y *= f0; a01.z *= f0; a01.w *= f0;
    a10.x *= f1; a10.y *= f1; a10.z *= f1; a10.w *= f1;
    a11.x *= f1; a11.y *= f1; a11.z *= f1; a11.w *= f1;
#pragma unroll
    for (int k = 0; k < 32; k++) {
        if (k >= kmax) break;
        float pa = sc[q0][k], pb = sc[q0 + 1][k];
        const float4* vr = kv4 + k * 32;
        int i0 = l16 ^ ((k >> 1) & 7);
        float4 v0 = vr[i0], v1 = vr[i0 + 16];
        a00.x += pa * v0.x; a00.y += pa * v0.y; a00.z += pa * v0.z; a00.w += pa * v0.w;
        a01.x += pa * v1.x; a01.y += pa * v1.y; a01.z += pa * v1.z; a01.w += pa * v1.w;
        a10.x += pb * v0.x; a10.y += pb * v0.y; a10.z += pb * v0.z; a10.w += pb * v0.w;
        a11.x += pb * v1.x; a11.y += pb * v1.y; a11.z += pb * v1.z; a11.w += pb * v1.w;
    }
}

// ---------------- flash attention over one 128-key chunk --------------------
__global__ void __launch_bounds__(256, 2)
att1(const int* __restrict__ pk, const float* __restrict__ pks,
     const int* __restrict__ pvv, const float* __restrict__ pvs,
     float* __restrict__ out)
{
    __shared__ float4 qs4[32 * 32];
    __shared__ float4 kv4[32 * 32];
    __shared__ __align__(16) float4 qkst[32 * 32];
    __shared__ __align__(16) float4 qvst[32 * 32];
    __shared__ __align__(16) float sclK[32];
    __shared__ __align__(16) float sclV[32];
    __shared__ float sc[32][33];
    __shared__ float scP[32][33];
    __shared__ float fac[32];

    const int c = blockIdx.x, kvh = blockIdx.y, b = blockIdx.z;
    const int tid = threadIdx.x;
    const int rr = tid >> 3, lane8 = tid & 7;
    const int tx = tid & 15, ty = tid >> 4;
    const int q0 = 2 * ty, k0 = 2 * tx, s0 = tx & 7;
    const int l16 = tx;

    { // load queries (chunk-strided per lane)
        const float4* s4 = (const float4*)(g_q + ((long)(b * 8 + kvh) * 32 + rr) * 128);
#pragma unroll
        for (int i = 0; i < 4; i++) qs4[rr * 32 + lane8 + 8 * i] = s4[lane8 + 8 * i];
    }

    float4 a00 = {0.f, 0.f, 0.f, 0.f}, a01 = a00, a10 = a00, a11 = a00;
    float m_run = -1e30f, l_run = 0.f;

    if (c < 32) {
        const long gbase = (long)(b * 8 + kvh) * 4096;
        int4 kiv[4], viv[4];
        float skc, svc;
        { // preload K(st=0)
            int pos = c * 128 + rr;
            const int4* p4 = (const int4*)(pk + (gbase + pos) * 128);
#pragma unroll
            for (int i = 0; i < 4; i++) kiv[i] = __ldcs(p4 + lane8 + 8 * i);
            skc = pks[gbase + pos];
        }
#pragma unroll 1
        for (int st = 0; st < 4; st++) {
            const int pos = c * 128 + st * 32 + rr;
            const int pos0 = c * 128 + st * 32;
            requant_smem(kiv, skc, rr, lane8, kv4, qkst, sclK);
            {
                const int4* p4 = (const int4*)(pvv + (gbase + pos) * 128);
#pragma unroll
                for (int i = 0; i < 4; i++) viv[i] = __ldcs(p4 + lane8 + 8 * i);
                svc = pvs[gbase + pos];
            }
            if (st < 3) {
                const int4* p4 = (const int4*)(pk + (gbase + pos + 32) * 128);
#pragma unroll
                for (int i = 0; i < 4; i++) kiv[i] = __ldcs(p4 + lane8 + 8 * i);
                skc = pks[gbase + pos + 32];
            }
            __syncthreads();
            if (tid == 0) {
                issue_bulk(out, OFF_KI8, OFF_KS, b, kvh, pos0, qkst, sclK);
                BULK_WAIT_READ1();
            }
            scores_past(qs4, kv4, sc, scP, tid);
            __syncthreads();
            softmax_past(sc, scP, fac, rr, lane8, m_run, l_run);
            requant_smem(viv, svc, rr, lane8, kv4, qvst, sclV);
            __syncthreads();
            if (tid == 0) {
                issue_bulk(out, OFF_VI8, OFF_VS, b, kvh, pos0, qvst, sclV);
                BULK_WAIT_READ1();
            }
            pv_phase(kv4, sc, fac, q0, l16, 32, a00, a01, a10, a11);
            __syncthreads();
        }
        if (tid == 0) BULK_WAIT_ALL();
    } else {
        const int swz = (rr >> 1) & 7;
        { // K (8 new rows, rest zero)
            float4 z = {0.f, 0.f, 0.f, 0.f};
            if (rr < 8) {
                const float4* s4 = (const float4*)(g_knew + ((long)(b * 8 + kvh) * 8 + rr) * 128);
#pragma unroll
                for (int i = 0; i < 4; i++) kv4[rr * 32 + ((lane8 + 8 * i) ^ swz)] = s4[lane8 + 8 * i];
            } else {
#pragma unroll
                for (int i = 0; i < 4; i++) kv4[rr * 32 + ((lane8 + 8 * i) ^ swz)] = z;
            }
        }
        __syncthreads();
        scores_phase(qs4, kv4, sc, q0, k0, s0, 1);
        __syncthreads();
        softmax_phase(sc, fac, rr, lane8, m_run, l_run);
        { // V
            float4 z = {0.f, 0.f, 0.f, 0.f};
            if (rr < 8) {
                const float4* s4 = (const float4*)(g_vnew + ((long)(b * 8 + kvh) * 8 + rr) * 128);
#pragma unroll
                for (int i = 0; i < 4; i++) kv4[rr * 32 + ((lane8 + 8 * i) ^ swz)] = s4[lane8 + 8 * i];
            } else {
#pragma unroll
                for (int i = 0; i < 4; i++) kv4[rr * 32 + ((lane8 + 8 * i) ^ swz)] = z;
            }
        }
        __syncthreads();
        pv_phase(kv4, sc, fac, q0, l16, 8, a00, a01, a10, a11);
    }

    // write partials
    {
        const long base = ((long)(b * 8 + kvh) * NCH + c) * 32;
        float4* g4 = (float4*)g_acc;
        g4[(base + q0) * 32 + l16]          = a00;
        g4[(base + q0) * 32 + l16 + 16]     = a01;
        g4[(base + q0 + 1) * 32 + l16]      = a10;
        g4[(base + q0 + 1) * 32 + l16 + 16] = a11;
        if (lane8 == 0) {
            g_m[base + rr] = m_run;
            g_l[base + rr] = l_run;
        }
    }
}

// --------- combine chunk partials: one warp per (qi, kvh, b) ----------------
// R15 form (no syncs) + maxed register budget for deep load batching + __ldcs.
__global__ void __launch_bounds__(256, 1) att2()
{
    const int gw = (blockIdx.x * blockDim.x + threadIdx.x) >> 5;  // 0..2047
    const int d4 = threadIdx.x & 31;
    const int qi = gw & 31, kvh = (gw >> 5) & 7, b = gw >> 8;
    const long base = ((long)(b * 8 + kvh) * NCH) * 32 + qi;

    float M = -1e30f;
#pragma unroll
    for (int c = 0; c < NCH; c++) M = fmaxf(M, g_m[base + (long)c * 32]);
    float L = 0.f;
    float4 o = {0.f, 0.f, 0.f, 0.f};
    const float4* g4 = (const float4*)g_acc;
#pragma unroll
    for (int c = 0; c < NCH; c++) {
        float w = expf(g_m[base + (long)c * 32] - M);
        L += __ldcs(&g_l[base + (long)c * 32]) * w;
        float4 v = __ldcs(&g4[(base + (long)c * 32) * 32 + d4]);
        o.x += v.x * w; o.y += v.y * w; o.z += v.z * w; o.w += v.w * w;
    }
    float4 res;
    res.x = __fdiv_rn(o.x, L);
    res.y = __fdiv_rn(o.y, L);
    res.z = __fdiv_rn(o.z, L);
    res.w = __fdiv_rn(o.w, L);
    int h = kvh * 4 + (qi >> 3), t = qi & 7;
    *(float4*)(g_attout + (long)(b * 8 + t) * 4096 + h * 128 + d4 * 4) = res;
}

// ---------------- host launcher -------------------------------------------
extern "C" void kernel_launch(void* const* d_in, const int* in_sizes, int n_in,
                              void* d_out, int out_size)
{
    const float* x   = (const float*)d_in[0];
    const float* Wq  = (const float*)d_in[1];
    const float* Wkv = (const float*)d_in[2];
    const float* Wo  = (const float*)d_in[3];
    const int*   pk  = (const int*)d_in[4];
    const float* pks = (const float*)d_in[5];
    const int*   pv  = (const int*)d_in[6];
    const float* pvs = (const float*)d_in[7];
    float* out = (float*)d_out;

    gemm64<<<dim3(96, NSPL), 256>>>(x, 0, Wq, 4096, 4096, Wkv, 2048, 6144, 4096, 512);

    rope_quant<<<3072, 128>>>(out);

    att1<<<dim3(NCH, NKV, BB), 256>>>(pk, pks, pv, pvs, out);

    att2<<<256, 256>>>();

    gemm64<<<dim3(64, NSPL2), 256>>>(x, 1, Wo, 4096, 4096, Wo, 4096, 4096, 4096, 256);
    reduce_out<<<256, 256>>>(out);
}